// round 6
// baseline (speedup 1.0000x reference)
#include <cuda_runtime.h>
#include <cstdint>

// ---------------------------------------------------------------------------
// CharacterEmbeddingLayer via vocabulary factorization:
//   conv dot-products depend only on (char id, piece, filter) -> precompute
//   PP[char][piece][filter] once (96x14x100), then conv = table adds + max,
//   and tanh is monotonic so tanh moves outside the max.
// Round 5: cp.async double-buffered staging everywhere; head reworked to
//   2 channels/thread (crossbar:fma <= 1) with 32 tokens/CTA.
// ---------------------------------------------------------------------------

#define NTOK  25600      // 64*400 tokens

typedef unsigned long long u64;

// PP table: [13 filter-chunks][96 chars][14 pieces][8 filters]
__device__ float g_pp[13 * 96 * 14 * 8];
// conv outputs: [NTOK][400]
__device__ float g_outs[(size_t)NTOK * 400];

// ---------------- packed fp32x2 + async helpers -----------------------------
__device__ __forceinline__ void ffma2(u64 &acc, u64 a, u64 b) {
    asm("fma.rn.f32x2 %0, %1, %2, %0;" : "+l"(acc) : "l"(a), "l"(b));
}
__device__ __forceinline__ u64 fadd2(u64 a, u64 b) {
    u64 r; asm("add.rn.f32x2 %0, %1, %2;" : "=l"(r) : "l"(a), "l"(b)); return r;
}
__device__ __forceinline__ void unpack2(u64 v, float &lo, float &hi) {
    asm("mov.b64 {%0, %1}, %2;" : "=f"(lo), "=f"(hi) : "l"(v));
}
__device__ __forceinline__ float hadd2(u64 v) {
    float lo, hi; unpack2(v, lo, hi); return lo + hi;
}
__device__ __forceinline__ float tanh_fast(float x) {
    float y;
    asm("tanh.approx.f32 %0, %1;" : "=f"(y) : "f"(x));
    return y;
}
__device__ __forceinline__ uint32_t smem_u32(const void* p) {
    return (uint32_t)__cvta_generic_to_shared(p);
}
__device__ __forceinline__ void cp16(uint32_t dst, const void* src) {
    asm volatile("cp.async.ca.shared.global [%0], [%1], 16;" :: "r"(dst), "l"(src));
}
__device__ __forceinline__ void cp8(uint32_t dst, const void* src) {
    asm volatile("cp.async.ca.shared.global [%0], [%1], 8;" :: "r"(dst), "l"(src));
}
__device__ __forceinline__ void cp_commit() {
    asm volatile("cp.async.commit_group;");
}
template<int N> __device__ __forceinline__ void cp_wait() {
    asm volatile("cp.async.wait_group %0;" :: "n"(N));
}

// ---------------------------------------------------------------------------
// Kernel A: precompute PP.  grid = (96 chars, 14 pieces), 128 threads.
// ---------------------------------------------------------------------------
__global__ void pp_kernel(const float* __restrict__ cv,
                          const float* __restrict__ f2, const float* __restrict__ f3,
                          const float* __restrict__ f4, const float* __restrict__ f5)
{
    __shared__ float scv[64];
    const int c  = blockIdx.x;
    const int pg = blockIdx.y;
    const int j  = threadIdx.x;
    if (j < 64) scv[j] = __ldg(cv + c * 64 + j);
    __syncthreads();

    if (j < 104) {
        float s = 0.0f;
        if (j < 100) {
            const float* fp; int pl, RL;
            if (pg < 2)      { fp = f2; pl = pg;     RL = 2; }
            else if (pg < 5) { fp = f3; pl = pg - 2; RL = 3; }
            else if (pg < 9) { fp = f4; pl = pg - 5; RL = 4; }
            else             { fp = f5; pl = pg - 9; RL = 5; }
            const float4* fr = reinterpret_cast<const float4*>(fp + (j * RL + pl) * 64);
            #pragma unroll 4
            for (int q = 0; q < 16; q++) {
                const float4 fv = __ldg(fr + q);
                s += scv[4*q]   * fv.x + scv[4*q+1] * fv.y
                   + scv[4*q+2] * fv.z + scv[4*q+3] * fv.w;
            }
        }
        g_pp[(((j >> 3) * 96 + c) * 14 + pg) * 8 + (j & 7)] = s;
    }
}

// ---------------------------------------------------------------------------
// Kernel B: conv as table sums.  grid = 400 (64 tokens/CTA), 256 threads.
// thread = (token t = tid>>2, filter-pair j2 = tid&3).  13 chunks of 8 filters,
// cp.async double-buffered. smem rows (c,pg) = 5 u64 (4 data + 1 pad, 40B).
// ---------------------------------------------------------------------------
#define TB1  256
#define CHUNK_U64 (96 * 14 * 5)            // 6720 u64 per buffer
#define SMEMB_BYTES (2 * CHUNK_U64 * 8)    // 107520 B

__device__ __forceinline__ void stage_chunk(uint32_t sbuf,
                                            const float* __restrict__ src, int tid)
{
    #pragma unroll 1
    for (int i = tid; i < 5376; i += TB1) {       // 1344 rows x 4 u64
        const int r = i >> 2, e = i & 3;
        cp8(sbuf + (uint32_t)(r * 5 + e) * 8u, src + 2 * i);
    }
}

template<int W, int PB, int BOFF>
__device__ __forceinline__ void branch_sum(const u64* __restrict__ s_pp,
                                           const int (&bix)[16],
                                           float* __restrict__ orow,
                                           int g, int j2)
{
    constexpr int L = 17 - W;
    float m0 = -1e30f, m1 = -1e30f;
    #pragma unroll
    for (int l = 0; l < L; l++) {
        u64 a = s_pp[bix[l] + PB * 5];
        #pragma unroll
        for (int p = 1; p < W; p++)
            a = fadd2(a, s_pp[bix[l + p] + (PB + p) * 5]);
        float lo, hi; unpack2(a, lo, hi);
        m0 = fmaxf(m0, lo);
        m1 = fmaxf(m1, hi);
    }
    if (g < 12 || j2 < 2) {     // chunk 12: only filters 96..99 are real
        float2 r;
        r.x = tanh_fast(m0);
        r.y = tanh_fast(m1);
        *reinterpret_cast<float2*>(orow + BOFF + g * 8 + j2 * 2) = r;
    }
}

__global__ void __launch_bounds__(TB1, 2)
conv_sum_kernel(const int* __restrict__ idxs)
{
    extern __shared__ u64 s_pp2[];
    u64* buf0 = s_pp2;
    u64* buf1 = s_pp2 + CHUNK_U64;
    const uint32_t sb0 = smem_u32(buf0);
    const uint32_t sb1 = smem_u32(buf1);

    const int tid = threadIdx.x;
    const int j2  = tid & 3;
    const int token = blockIdx.x * 64 + (tid >> 2);

    int bix[16];
    {
        const int4* ip4 = reinterpret_cast<const int4*>(idxs + token * 16);
        const int4 A = __ldg(ip4 + 0), B = __ldg(ip4 + 1);
        const int4 C = __ldg(ip4 + 2), D = __ldg(ip4 + 3);
        bix[ 0] = A.x * 70 + j2; bix[ 1] = A.y * 70 + j2;
        bix[ 2] = A.z * 70 + j2; bix[ 3] = A.w * 70 + j2;
        bix[ 4] = B.x * 70 + j2; bix[ 5] = B.y * 70 + j2;
        bix[ 6] = B.z * 70 + j2; bix[ 7] = B.w * 70 + j2;
        bix[ 8] = C.x * 70 + j2; bix[ 9] = C.y * 70 + j2;
        bix[10] = C.z * 70 + j2; bix[11] = C.w * 70 + j2;
        bix[12] = D.x * 70 + j2; bix[13] = D.y * 70 + j2;
        bix[14] = D.z * 70 + j2; bix[15] = D.w * 70 + j2;
    }

    float* orow = g_outs + (size_t)token * 400;

    stage_chunk(sb0, g_pp, tid);
    cp_commit();

    #pragma unroll 1
    for (int g = 0; g < 13; g++) {
        if (g < 12) {
            stage_chunk((g & 1) ? sb0 : sb1, g_pp + (g + 1) * 10752, tid);
            cp_commit();
            cp_wait<1>();
        } else {
            cp_wait<0>();
        }
        __syncthreads();
        const u64* sp = (g & 1) ? buf1 : buf0;
        branch_sum<2, 0,   0>(sp, bix, orow, g, j2);
        branch_sum<3, 2, 100>(sp, bix, orow, g, j2);
        branch_sum<4, 5, 200>(sp, bix, orow, g, j2);
        branch_sum<5, 9, 300>(sp, bix, orow, g, j2);
        __syncthreads();                  // buffer g&1 free for restage
    }
}

// ---------------------------------------------------------------------------
// Kernel C: head.  256 threads: c2 = tid&63 -> channels (c2, c2+64),
// tq = tid>>6 -> 8-token group; 32 tokens/CTA, grid 800.
// cp.async double-buffered weight staging; x broadcasts feed 2-4 acc sets.
// ---------------------------------------------------------------------------
#define T2    256
#define TOK2  32
#define XP    132                          // s_x row pitch (floats)
#define WP    44                           // staged row pitch (floats), 176B
#define WBUF  (256 * WP)                   // floats per buffer (11264)
#define SMEM2_BYTES ((TOK2 * XP + 2 * WBUF) * 4)   // 107008 B

__global__ void __launch_bounds__(T2, 2)
head_kernel(const float* __restrict__ wp,
            const float* __restrict__ tw0, const float* __restrict__ tb0,
            const float* __restrict__ tw1, const float* __restrict__ tb1,
            const float* __restrict__ gw0, const float* __restrict__ gb0,
            const float* __restrict__ gw1, const float* __restrict__ gb1,
            float* __restrict__ out)
{
    extern __shared__ float sm2[];
    float* s_x = sm2;                      // [32][132]
    float* w0  = s_x + TOK2 * XP;          // buffer 0: [256][44]
    float* w1  = w0 + WBUF;                // buffer 1
    const uint32_t wb[2] = { smem_u32(w0), smem_u32(w1) };
    float* const wf[2] = { w0, w1 };

    const int tid  = threadIdx.x;
    const int c2   = tid & 63;             // channels c2 and c2+64
    const int tq   = tid >> 6;             // token group 0..3
    const int tok0 = blockIdx.x * TOK2;

    // ---- projection: 10 chunks of 40 over k=400 --------------------------
    // staged layout: rows 0..127 = wp rows (chunk cols), rows 128..159 = outs.
    auto stage_proj = [&](int kc, uint32_t b) {
        #pragma unroll 1
        for (int i = tid; i < 1280; i += T2) {         // 128 rows x 10 quads
            const int r = i / 10, q = i - r * 10;
            cp16(b + (uint32_t)(r * WP + 4 * q) * 4u,
                 wp + r * 400 + kc * 40 + 4 * q);
        }
        #pragma unroll 1
        for (int i = tid; i < 320; i += T2) {          // 32 rows x 10 quads
            const int r = i / 10, q = i - r * 10;
            cp16(b + (uint32_t)((128 + r) * WP + 4 * q) * 4u,
                 g_outs + (size_t)(tok0 + r) * 400 + kc * 40 + 4 * q);
        }
    };

    u64 a0[8], a1[8];
    #pragma unroll
    for (int i = 0; i < 8; i++) { a0[i] = 0ull; a1[i] = 0ull; }

    stage_proj(0, wb[0]);
    cp_commit();
    #pragma unroll 1
    for (int kc = 0; kc < 10; kc++) {
        if (kc < 9) { stage_proj(kc + 1, wb[(kc + 1) & 1]); cp_commit(); cp_wait<1>(); }
        else        { cp_wait<0>(); }
        __syncthreads();
        const float* b  = wf[kc & 1];
        const float* wA = b + c2 * WP;
        const float* wB = b + (c2 + 64) * WP;
        const float* xb = b + 128 * WP + (tq * 8) * WP;
        #pragma unroll
        for (int k4 = 0; k4 < 10; k4++) {
            const ulonglong2 wa = *reinterpret_cast<const ulonglong2*>(wA + 4 * k4);
            const ulonglong2 wv = *reinterpret_cast<const ulonglong2*>(wB + 4 * k4);
            #pragma unroll
            for (int i = 0; i < 8; i++) {
                const ulonglong2 xv = *reinterpret_cast<const ulonglong2*>(xb + i * WP + 4 * k4);
                ffma2(a0[i], xv.x, wa.x); ffma2(a0[i], xv.y, wa.y);
                ffma2(a1[i], xv.x, wv.x); ffma2(a1[i], xv.y, wv.y);
            }
        }
        __syncthreads();
    }

    float x0[8], x1[8];
    #pragma unroll
    for (int i = 0; i < 8; i++) {
        x0[i] = hadd2(a0[i]);  s_x[(tq * 8 + i) * XP + c2]      = x0[i];
        x1[i] = hadd2(a1[i]);  s_x[(tq * 8 + i) * XP + c2 + 64] = x1[i];
    }
    __syncthreads();

    // ---- 2 highway layers: 4 chunks of 32 over k=128 ---------------------
    const float* TW[2] = { tw0, tw1 };
    const float* TBv[2] = { tb0, tb1 };
    const float* GW[2] = { gw0, gw1 };
    const float* GBv[2] = { gb0, gb1 };

    #pragma unroll 1
    for (int layer = 0; layer < 2; layer++) {
        const float* tw = TW[layer];
        const float* gw = GW[layer];
        // staged layout: rows 0..127 = tw, rows 128..255 = gw.
        auto stage_hwy = [&](int kc, uint32_t b) {
            #pragma unroll 1
            for (int i = tid; i < 2048; i += T2) {     // 256 rows x 8 quads
                const int r = i >> 3, q = i & 7;
                const float* src = (r < 128)
                    ? tw + r * 128 + kc * 32 + 4 * q
                    : gw + (r - 128) * 128 + kc * 32 + 4 * q;
                cp16(b + (uint32_t)(r * WP + 4 * q) * 4u, src);
            }
        };

        u64 at0[8], at1[8], ag0[8], ag1[8];
        #pragma unroll
        for (int i = 0; i < 8; i++) { at0[i] = at1[i] = ag0[i] = ag1[i] = 0ull; }

        stage_hwy(0, wb[0]);
        cp_commit();
        #pragma unroll 1
        for (int kc = 0; kc < 4; kc++) {
            if (kc < 3) { stage_hwy(kc + 1, wb[(kc + 1) & 1]); cp_commit(); cp_wait<1>(); }
            else        { cp_wait<0>(); }
            __syncthreads();
            const float* b = wf[kc & 1];
            #pragma unroll
            for (int k4 = 0; k4 < 8; k4++) {
                const ulonglong2 wt0 = *reinterpret_cast<const ulonglong2*>(b + c2 * WP + 4 * k4);
                const ulonglong2 wt1 = *reinterpret_cast<const ulonglong2*>(b + (c2 + 64) * WP + 4 * k4);
                const ulonglong2 wg0 = *reinterpret_cast<const ulonglong2*>(b + (128 + c2) * WP + 4 * k4);
                const ulonglong2 wg1 = *reinterpret_cast<const ulonglong2*>(b + (192 + c2) * WP + 4 * k4);
                #pragma unroll
                for (int i = 0; i < 8; i++) {
                    const ulonglong2 xv = *reinterpret_cast<const ulonglong2*>(
                        s_x + (tq * 8 + i) * XP + kc * 32 + 4 * k4);
                    ffma2(at0[i], xv.x, wt0.x); ffma2(at0[i], xv.y, wt0.y);
                    ffma2(at1[i], xv.x, wt1.x); ffma2(at1[i], xv.y, wt1.y);
                    ffma2(ag0[i], xv.x, wg0.x); ffma2(ag0[i], xv.y, wg0.y);
                    ffma2(ag1[i], xv.x, wg1.x); ffma2(ag1[i], xv.y, wg1.y);
                }
            }
            __syncthreads();              // buffer kc&1 free for restage
        }

        const float tb0v = __ldg(TBv[layer] + c2);
        const float tb1v = __ldg(TBv[layer] + c2 + 64);
        const float gb0v = __ldg(GBv[layer] + c2);
        const float gb1v = __ldg(GBv[layer] + c2 + 64);
        #pragma unroll
        for (int i = 0; i < 8; i++) {
            const float tv0 = fmaxf(hadd2(at0[i]) + tb0v, 0.0f);
            const float tv1 = fmaxf(hadd2(at1[i]) + tb1v, 0.0f);
            const float g0  = 0.5f * tanh_fast(0.5f * (hadd2(ag0[i]) + gb0v)) + 0.5f;
            const float g1  = 0.5f * tanh_fast(0.5f * (hadd2(ag1[i]) + gb1v)) + 0.5f;
            x0[i] = g0 * tv0 + (1.0f - g0) * x0[i];
            x1[i] = g1 * tv1 + (1.0f - g1) * x1[i];
            s_x[(tq * 8 + i) * XP + c2]      = x0[i];
            s_x[(tq * 8 + i) * XP + c2 + 64] = x1[i];
        }
        __syncthreads();
    }

    #pragma unroll
    for (int i = 0; i < 8; i++) {
        out[(size_t)(tok0 + tq * 8 + i) * 128 + c2]      = x0[i];
        out[(size_t)(tok0 + tq * 8 + i) * 128 + c2 + 64] = x1[i];
    }
}

// ---------------------------------------------------------------------------
extern "C" void kernel_launch(void* const* d_in, const int* in_sizes, int n_in,
                              void* d_out, int out_size)
{
    const int*   idxs = (const int*)  d_in[0];
    const float* cv   = (const float*)d_in[1];
    const float* f2   = (const float*)d_in[2];
    const float* f3   = (const float*)d_in[3];
    const float* f4   = (const float*)d_in[4];
    const float* f5   = (const float*)d_in[5];
    const float* wp   = (const float*)d_in[6];
    const float* tw0  = (const float*)d_in[7];
    const float* tb0  = (const float*)d_in[8];
    const float* tw1  = (const float*)d_in[9];
    const float* tb1  = (const float*)d_in[10];
    const float* gw0  = (const float*)d_in[11];
    const float* gb0  = (const float*)d_in[12];
    const float* gw1  = (const float*)d_in[13];
    const float* gb1  = (const float*)d_in[14];
    float* out = (float*)d_out;

    static bool attr_done = false;
    if (!attr_done) {
        cudaFuncSetAttribute(conv_sum_kernel,
                             cudaFuncAttributeMaxDynamicSharedMemorySize, SMEMB_BYTES);
        cudaFuncSetAttribute(head_kernel,
                             cudaFuncAttributeMaxDynamicSharedMemorySize, SMEM2_BYTES);
        attr_done = true;
    }

    pp_kernel<<<dim3(96, 14), 128>>>(cv, f2, f3, f4, f5);
    conv_sum_kernel<<<NTOK / 64, TB1, SMEMB_BYTES>>>(idxs);
    head_kernel<<<NTOK / TOK2, T2, SMEM2_BYTES>>>(wp, tw0, tb0, tw1, tb1,
                                                  gw0, gb0, gw1, gb1, out);
}